// round 3
// baseline (speedup 1.0000x reference)
#include <cuda_runtime.h>
#include <cstdint>

#define T_LEN   730
#define B_LEN   1000
#define NMUL    8
#define LENF    15
#define NEARZERO 1e-5f

#define SCAN_BLOCKS 125          // 125*32 = 4000 threads, 2 chains each
#define UH_BLOCKS   32           // 32*32 = 1024 >= 1000 basins
#define UG 10
#define NGROUPS 73               // 73*10 = 730

// Scratch (device globals: allocation-free)
__device__ float g_qsurf[T_LEN * B_LEN];
__device__ float g_qgw  [T_LEN * B_LEN];
__device__ float g_uh   [B_LEN * LENF];

__device__ __forceinline__ float f_sqrt_approx(float x) {
    float r; asm("sqrt.approx.f32 %0, %1;" : "=f"(r) : "f"(x)); return r;
}
__device__ __forceinline__ float f_ex2(float x) {
    float r; asm("ex2.approx.f32 %0, %1;" : "=f"(r) : "f"(x)); return r;
}
// sum over the 4 lanes of a basin quad (xor 1, xor 2)
__device__ __forceinline__ float rsum4(float v) {
    v += __shfl_xor_sync(0xffffffffu, v, 1);
    v += __shfl_xor_sync(0xffffffffu, v, 2);
    return v;
}

// ---------------------------------------------------------------------------
// unit hydrograph for one basin (runs in extra blocks, hidden behind scan)
// ---------------------------------------------------------------------------
__device__ void uh_for_basin(const float* __restrict__ raw, int b) {
    float ra = raw[b * 34 + 32] * 2.9f;
    float rb = raw[b * 34 + 33] * 6.5f;
    float aa    = fmaxf(ra, 0.0f) + 0.1f;
    float theta = fmaxf(rb, 0.0f) + 0.5f;
    float lg   = lgammaf(aa);
    float lth  = logf(theta);
    float ivth = 1.0f / theta;
    float w[LENF];
    float s = 0.0f;
#pragma unroll
    for (int k = 0; k < LENF; ++k) {
        float t = (float)k + 0.5f;
        float lw = (aa - 1.0f) * logf(t) - t * ivth - lg - aa * lth;
        w[k] = expf(lw);
        s += w[k];
    }
    float inv = 1.0f / s;
#pragma unroll
    for (int k = 0; k < LENF; ++k)
        g_uh[b * LENF + k] = w[k] * inv;
}

// ---------------------------------------------------------------------------
// Fused scan: blocks [0,125) run the abcd recurrence, 2 chains per thread,
// 4 lanes per basin. Blocks [125,157) compute the unit hydrograph.
// ---------------------------------------------------------------------------
__global__ void __launch_bounds__(32) fused_scan_kernel(
    const float* __restrict__ x,      // (T,B,2)
    const float* __restrict__ raw,    // (B,34)
    float* __restrict__ out)          // (T,B,6)
{
    if (blockIdx.x >= SCAN_BLOCKS) {
        int b = (blockIdx.x - SCAN_BLOCKS) * 32 + threadIdx.x;
        if (b < B_LEN) uh_for_basin(raw, b);
        return;
    }

    int g = blockIdx.x * 32 + threadIdx.x;   // 0..3999
    int b = g >> 2;
    int q = g & 3;                            // lane-in-quad
    int m0 = q;                               // channel A
    int m1 = q + 4;                           // channel B

    // channel A params
    float a0  = fmaf(raw[b*34 +      m0], 0.9f, 0.1f);
    float bb0 = fmaf(raw[b*34 +  8 + m0], 450.0f, 50.0f);
    float c0  = raw[b*34 + 16 + m0];
    float d0  = fmaf(raw[b*34 + 24 + m0], 0.89f, 0.01f);
    // channel B params
    float a1  = fmaf(raw[b*34 +      m1], 0.9f, 0.1f);
    float bb1 = fmaf(raw[b*34 +  8 + m1], 450.0f, 50.0f);
    float c1  = raw[b*34 + 16 + m1];
    float d1  = fmaf(raw[b*34 + 24 + m1], 0.89f, 0.01f);

    float inv2a0 = 0.5f / a0,  inv2a1 = 0.5f / a1;
    float binv2a0 = bb0 * inv2a0, binv2a1 = bb1 * inv2a1;
    float boa0 = bb0 / a0, boa1 = bb1 / a1;
    float nl2eob0 = -1.44269504088896f / bb0;
    float nl2eob1 = -1.44269504088896f / bb1;
    float onemc0 = 1.0f - c0, onemc1 = 1.0f - c1;
    float inv1pd0 = 1.0f / (1.0f + d0), inv1pd1 = 1.0f / (1.0f + d1);

    float S0v = 50.0f, G0v = 10.0f;
    float S1v = 50.0f, G1v = 10.0f;

    // per-lane output routing (full butterflies give every lane every sum)
    //   q0 -> qsurf mean (g_qsurf), q1 -> qgw mean (g_qgw),
    //   q2 -> AET mean (out+3),     q3 -> S mean (out+4) AND G mean (out+5)
    bool isq1 = (q == 1), isq2 = (q == 2), isq3 = (q == 3);
    float* sp;
    int sstride;
    if      (q == 0) { sp = g_qsurf + b;     sstride = B_LEN; }
    else if (q == 1) { sp = g_qgw   + b;     sstride = B_LEN; }
    else if (q == 2) { sp = out + b*6 + 3;   sstride = 6*B_LEN; }
    else             { sp = out + b*6 + 4;   sstride = 6*B_LEN; }
    float* sp2 = out + b*6 + 5;              // used only by q3

    const float2* __restrict__ xv = (const float2*)x;   // index t*B + b

    float2 cur[UG], nxt[UG];
#pragma unroll
    for (int i = 0; i < UG; ++i) cur[i] = __ldg(xv + i * B_LEN + b);

    for (int gi = 0; gi < NGROUPS; ++gi) {
        if (gi < NGROUPS - 1) {
            const float2* base = xv + (gi + 1) * UG * B_LEN + b;
#pragma unroll
            for (int i = 0; i < UG; ++i) nxt[i] = __ldg(base + i * B_LEN);
        }
#pragma unroll
        for (int i = 0; i < UG; ++i) {
            float p   = cur[i].x;
            float pet = cur[i].y;

            // channel A
            float W0    = p + S0v;
            float t0    = fmaf(W0, inv2a0, binv2a0);
            float arg0  = fmaxf(fmaf(t0, t0, -(W0 * boa0)), NEARZERO);
            float Y0    = t0 - f_sqrt_approx(arg0);
            float Sn0   = Y0 * f_ex2(pet * nl2eob0);
            float av0   = W0 - Y0;
            float qs0   = onemc0 * av0;
            float Gn0   = fmaf(c0, av0, G0v) * inv1pd0;
            float qg0   = d0 * Gn0;
            float ae0   = Y0 - Sn0;
            S0v = Sn0; G0v = Gn0;

            // channel B
            float W1    = p + S1v;
            float t1    = fmaf(W1, inv2a1, binv2a1);
            float arg1  = fmaxf(fmaf(t1, t1, -(W1 * boa1)), NEARZERO);
            float Y1    = t1 - f_sqrt_approx(arg1);
            float Sn1   = Y1 * f_ex2(pet * nl2eob1);
            float av1   = W1 - Y1;
            float qs1   = onemc1 * av1;
            float Gn1   = fmaf(c1, av1, G1v) * inv1pd1;
            float qg1   = d1 * Gn1;
            float ae1   = Y1 - Sn1;
            S1v = Sn1; G1v = Gn1;

            // five independent 2-stage butterfly sums over the quad
            float sQS = rsum4(qs0 + qs1);
            float sQG = rsum4(qg0 + qg1);
            float sAE = rsum4(ae0 + ae1);
            float sS  = rsum4(Sn0 + Sn1);
            float sG  = rsum4(Gn0 + Gn1);

            float v = sQS;
            if (isq1) v = sQG;
            if (isq2) v = sAE;
            if (isq3) v = sS;
            *sp = v * 0.125f;
            if (isq3) *sp2 = sG * 0.125f;
            sp  += sstride;
            sp2 += 6*B_LEN;
        }
        if (gi < NGROUPS - 1) {
#pragma unroll
            for (int i = 0; i < UG; ++i) cur[i] = nxt[i];
        }
    }
}

// ---------------------------------------------------------------------------
// Conv: causal 15-tap convolution of Qsurf & Qgw means; Qsim = sum (linear).
// One basin, 5 consecutive t per thread (730 = 146*5).
// ---------------------------------------------------------------------------
#define TPER 5
__global__ void conv_kernel(float* __restrict__ out) {
    int idx = blockIdx.x * blockDim.x + threadIdx.x;
    if (idx >= (T_LEN / TPER) * B_LEN) return;
    int b  = idx % B_LEN;
    int t0 = (idx / B_LEN) * TPER;

    float uh[LENF];
#pragma unroll
    for (int k = 0; k < LENF; ++k) uh[k] = __ldg(&g_uh[b * LENF + k]);

    float qs1[LENF - 1 + TPER];
    float qs2[LENF - 1 + TPER];
#pragma unroll
    for (int i = 0; i < LENF - 1 + TPER; ++i) {
        int tt = t0 - (LENF - 1) + i;
        bool ok = (tt >= 0);
        qs1[i] = ok ? __ldg(&g_qsurf[tt * B_LEN + b]) : 0.0f;
        qs2[i] = ok ? __ldg(&g_qgw  [tt * B_LEN + b]) : 0.0f;
    }
#pragma unroll
    for (int j = 0; j < TPER; ++j) {
        float a1 = 0.0f, a2 = 0.0f;
#pragma unroll
        for (int k = 0; k < LENF; ++k) {
            a1 = fmaf(uh[k], qs1[LENF - 1 + j - k], a1);
            a2 = fmaf(uh[k], qs2[LENF - 1 + j - k], a2);
        }
        float* o = out + (t0 + j) * (6 * B_LEN) + b * 6;
        o[0] = a1 + a2;   // routed Qsim (conv is linear)
        o[1] = a1;        // routed Qsurf
        o[2] = a2;        // routed Qgw
    }
}

// ---------------------------------------------------------------------------
extern "C" void kernel_launch(void* const* d_in, const int* in_sizes, int n_in,
                              void* d_out, int out_size) {
    const float* x   = (const float*)d_in[0];   // (730,1000,2)
    const float* raw = (const float*)d_in[1];   // (1000,34)
    float* out = (float*)d_out;                 // (730,1000,6)

    fused_scan_kernel<<<SCAN_BLOCKS + UH_BLOCKS, 32>>>(x, raw, out);
    int nconv = (T_LEN / TPER) * B_LEN;
    conv_kernel<<<(nconv + 255) / 256, 256>>>(out);
}

// round 4
// speedup vs baseline: 2.1057x; 2.1057x over previous
#include <cuda_runtime.h>
#include <cstdint>

#define T_LEN   730
#define B_LEN   1000
#define NMUL    8
#define LENF    15
#define NEARZERO 1e-5f

#define SCAN_BLOCKS 125          // 125*64 = 8000 chains (1 per thread)
#define UH_BLOCKS   16           // 16*64 = 1024 >= 1000 basins
#define UG 10                    // timesteps per prefetch group
#define NGROUPS 73               // 73*10 = 730

// Scratch (device globals: allocation-free)
__device__ float g_qsurf[T_LEN * B_LEN];
__device__ float g_qgw  [T_LEN * B_LEN];
__device__ float g_uh   [B_LEN * LENF];

__device__ __forceinline__ float f_sqrt_approx(float x) {
    float r; asm("sqrt.approx.f32 %0, %1;" : "=f"(r) : "f"(x)); return r;
}
__device__ __forceinline__ float f_ex2(float x) {
    float r; asm("ex2.approx.f32 %0, %1;" : "=f"(r) : "f"(x)); return r;
}
__device__ __forceinline__ float rsum8(float v) {
    v += __shfl_xor_sync(0xffffffffu, v, 1);
    v += __shfl_xor_sync(0xffffffffu, v, 2);
    v += __shfl_xor_sync(0xffffffffu, v, 4);
    return v;
}

// ---------------------------------------------------------------------------
// unit hydrograph for one basin (runs in extra blocks, hidden behind scan)
// ---------------------------------------------------------------------------
__device__ void uh_for_basin(const float* __restrict__ raw, int b) {
    float ra = raw[b * 34 + 32] * 2.9f;
    float rb = raw[b * 34 + 33] * 6.5f;
    float aa    = fmaxf(ra, 0.0f) + 0.1f;
    float theta = fmaxf(rb, 0.0f) + 0.5f;
    float lg   = lgammaf(aa);
    float lth  = logf(theta);
    float ivth = 1.0f / theta;
    float w[LENF];
    float s = 0.0f;
#pragma unroll
    for (int k = 0; k < LENF; ++k) {
        float t = (float)k + 0.5f;
        float lw = (aa - 1.0f) * logf(t) - t * ivth - lg - aa * lth;
        w[k] = expf(lw);
        s += w[k];
    }
    float inv = 1.0f / s;
#pragma unroll
    for (int k = 0; k < LENF; ++k)
        g_uh[b * LENF + k] = w[k] * inv;
}

// ---------------------------------------------------------------------------
// Fused scan (R1-proven core): blocks [0,125) run the abcd recurrence,
// 1 chain/thread, 8 lanes/basin, five independent rsum8 butterflies.
// Blocks [125,141) compute the unit hydrograph concurrently.
// ---------------------------------------------------------------------------
__global__ void __launch_bounds__(64, 4) fused_scan_kernel(
    const float* __restrict__ x,      // (T,B,2)
    const float* __restrict__ raw,    // (B,34)
    float* __restrict__ out)          // (T,B,6)
{
    if (blockIdx.x >= SCAN_BLOCKS) {
        int b = (blockIdx.x - SCAN_BLOCKS) * 64 + threadIdx.x;
        if (b < B_LEN) uh_for_basin(raw, b);
        return;
    }

    int g  = blockIdx.x * 64 + threadIdx.x;   // 0..7999
    int b  = g >> 3;
    int m  = g & 7;

    float r0 = raw[b * 34 +      m];
    float r1 = raw[b * 34 +  8 + m];
    float r2 = raw[b * 34 + 16 + m];
    float r3 = raw[b * 34 + 24 + m];
    float a   = fmaf(r0, 0.9f, 0.1f);
    float bb  = fmaf(r1, 450.0f, 50.0f);
    float c   = r2;
    float d   = fmaf(r3, 0.89f, 0.01f);

    float inv2a  = 0.5f / a;
    float binv2a = bb * inv2a;
    float boa    = bb / a;
    float nl2eob = -1.44269504088896f / bb;   // -log2(e)/b
    float onemc  = 1.0f - c;
    float inv1pd = 1.0f / (1.0f + d);

    float S = 50.0f, G = 10.0f;

    // lane -> output routing (Qsim dropped: reconstructed in conv by linearity)
    //  m0 -> Qsurf mean (g_qsurf), m1 -> Qgw mean (g_qgw),
    //  m2 -> AET mean (out+3), m3 -> S mean (out+4), m4 -> G mean (out+5)
    bool is1 = (m == 1), is2 = (m == 2), is3 = (m == 3), is4 = (m == 4);
    bool doStore = (m < 5);
    float* sp;
    int sstride;
    if      (m == 0) { sp = g_qsurf + b;       sstride = B_LEN; }
    else if (m == 1) { sp = g_qgw   + b;       sstride = B_LEN; }
    else if (m == 2) { sp = out + b * 6 + 3;   sstride = 6 * B_LEN; }
    else if (m == 3) { sp = out + b * 6 + 4;   sstride = 6 * B_LEN; }
    else if (m == 4) { sp = out + b * 6 + 5;   sstride = 6 * B_LEN; }
    else             { sp = g_qsurf + b;       sstride = B_LEN; }  // inert

    const float2* __restrict__ xv = (const float2*)x;   // index t*B + b

    float2 cur[UG], nxt[UG];
#pragma unroll
    for (int i = 0; i < UG; ++i) cur[i] = __ldg(xv + i * B_LEN + b);

    for (int gi = 0; gi < NGROUPS; ++gi) {
        if (gi < NGROUPS - 1) {
            const float2* base = xv + (gi + 1) * UG * B_LEN + b;
#pragma unroll
            for (int i = 0; i < UG; ++i) nxt[i] = __ldg(base + i * B_LEN);
        }
#pragma unroll
        for (int i = 0; i < UG; ++i) {
            float p   = cur[i].x;
            float pet = cur[i].y;

            float W    = p + S;
            float term = fmaf(W, inv2a, binv2a);
            float wboa = W * boa;
            float arg  = fmaf(term, term, -wboa);
            arg        = fmaxf(arg, NEARZERO);
            float sq   = f_sqrt_approx(arg);
            float Y    = term - sq;
            float ef   = f_ex2(pet * nl2eob);
            float Snew = Y * ef;
            float avail = W - Y;
            float Qsurf = onemc * avail;
            float Gnew  = fmaf(c, avail, G) * inv1pd;
            float Qgw   = d * Gnew;
            float AET   = Y - Snew;
            S = Snew;
            G = Gnew;

            // five independent 3-stage butterflies (proven-fast form)
            float Qss = rsum8(Qsurf);
            float Qgs = rsum8(Qgw);
            float Aes = rsum8(AET);
            float Ss  = rsum8(Snew);
            float Gs  = rsum8(Gnew);

            float v = Qss;
            if (is1) v = Qgs;
            if (is2) v = Aes;
            if (is3) v = Ss;
            if (is4) v = Gs;
            v *= 0.125f;
            if (doStore) *sp = v;
            sp += sstride;
        }
        if (gi < NGROUPS - 1) {
#pragma unroll
            for (int i = 0; i < UG; ++i) cur[i] = nxt[i];
        }
    }
}

// ---------------------------------------------------------------------------
// Conv: one (t, basin) output per thread — maximize latency hiding.
// Qsim (col 0) = col1 + col2 by linearity of the convolution.
// ---------------------------------------------------------------------------
__global__ void __launch_bounds__(256) conv_kernel(float* __restrict__ out) {
    int idx = blockIdx.x * blockDim.x + threadIdx.x;
    if (idx >= T_LEN * B_LEN) return;
    int b = idx % B_LEN;
    int t = idx / B_LEN;

    const float* __restrict__ uh = g_uh + b * LENF;
    float a1 = 0.0f, a2 = 0.0f;
    int kmax = (t < LENF - 1) ? t : (LENF - 1);
#pragma unroll
    for (int k = 0; k < LENF; ++k) {
        if (k <= kmax) {
            float w  = __ldg(&uh[k]);
            int   tt = t - k;
            a1 = fmaf(w, __ldg(&g_qsurf[tt * B_LEN + b]), a1);
            a2 = fmaf(w, __ldg(&g_qgw  [tt * B_LEN + b]), a2);
        }
    }
    float* o = out + t * (6 * B_LEN) + b * 6;
    o[0] = a1 + a2;
    o[1] = a1;
    o[2] = a2;
}

// Empty kernels: shift launch indices so ncu (-s 5 -c 1) captures the scan.
__global__ void dummy_kernel() {}

// ---------------------------------------------------------------------------
extern "C" void kernel_launch(void* const* d_in, const int* in_sizes, int n_in,
                              void* d_out, int out_size) {
    const float* x   = (const float*)d_in[0];   // (730,1000,2)
    const float* raw = (const float*)d_in[1];   // (1000,34)
    float* out = (float*)d_out;                 // (730,1000,6)

    dummy_kernel<<<1, 32>>>();
    fused_scan_kernel<<<SCAN_BLOCKS + UH_BLOCKS, 64>>>(x, raw, out);
    dummy_kernel<<<1, 32>>>();
    int n = T_LEN * B_LEN;
    conv_kernel<<<(n + 255) / 256, 256>>>(out);
}